// round 1
// baseline (speedup 1.0000x reference)
#include <cuda_runtime.h>
#include <cuda_bf16.h>

// Problem constants (all compile-time):
// T=50, H=W=8, NH=16, B=8, TP=TF=8, HIDDEN=512, RPE_COEF=16, table rows = 99*15*15 = 22275
#define NROW   22275
#define NHEAD  16
#define HIDDEN 512

// Scratch: activated+transposed MLP table: g_rpt[nh][row] = 16*sigmoid(rpt[row][nh])
__device__ float g_rpt[NHEAD * NROW];

// ---------------------------------------------------------------------------
// Kernel 1: cpb MLP over the coords table, fused 16*sigmoid, transposed store.
//   rpt = relu(rct @ W1 + b1) @ W2 ;  g_rpt[nh][row] = 16*sigmoid(rpt[row][nh])
// 16 rows per block, 128 threads. Hidden stored bf16x2 in smem (numerically
// safe: hidden ~1e-2, final rel err contribution ~1e-5).
// ---------------------------------------------------------------------------
__global__ void __launch_bounds__(128) mlp_kernel(
    const float* __restrict__ rct,   // [NROW, 3]
    const float* __restrict__ W1,    // [3, 512]
    const float* __restrict__ b1,    // [512]
    const float* __restrict__ W2)    // [512, 16]
{
    __shared__ float        sW2[HIDDEN * NHEAD];      // 32 KB
    __shared__ unsigned int sh [HIDDEN * 8];          // 16 KB: bf16x2 per (h, row-pair)

    const int t    = threadIdx.x;      // 0..127
    const int row0 = blockIdx.x * 16;

    // Load W2 into smem (vectorized)
    {
        float4*       dst = reinterpret_cast<float4*>(sW2);
        const float4* src = reinterpret_cast<const float4*>(W2);
        #pragma unroll
        for (int i = t; i < (HIDDEN * NHEAD) / 4; i += 128) dst[i] = src[i];
    }

    // -------- Phase 1: hidden layer for this block's 16 rows --------
    {
        const int g  = t >> 4;          // row pair 0..7
        const int l  = t & 15;          // h-slot within stride-16 sweep
        const int r0 = row0 + 2 * g;
        const int r1 = r0 + 1;
        float c00 = 0.f, c01 = 0.f, c02 = 0.f;
        float c10 = 0.f, c11 = 0.f, c12 = 0.f;
        if (r0 < NROW) { c00 = __ldg(rct + r0 * 3 + 0);
                         c01 = __ldg(rct + r0 * 3 + 1);
                         c02 = __ldg(rct + r0 * 3 + 2); }
        if (r1 < NROW) { c10 = __ldg(rct + r1 * 3 + 0);
                         c11 = __ldg(rct + r1 * 3 + 1);
                         c12 = __ldg(rct + r1 * 3 + 2); }
        #pragma unroll 4
        for (int i = 0; i < HIDDEN / 16; i++) {
            const int h  = i * 16 + l;
            const float w0 = __ldg(W1 + h);
            const float w1 = __ldg(W1 + HIDDEN + h);
            const float w2 = __ldg(W1 + 2 * HIDDEN + h);
            const float bb = __ldg(b1 + h);
            const float h0 = fmaxf(fmaf(c02, w2, fmaf(c01, w1, fmaf(c00, w0, bb))), 0.f);
            const float h1 = fmaxf(fmaf(c12, w2, fmaf(c11, w1, fmaf(c10, w0, bb))), 0.f);
            // pack: low 16 bits = row r0's hidden, high 16 = row r1's hidden
            const unsigned int lo = __bfloat16_as_ushort(__float2bfloat16(h0));
            const unsigned int hi = __bfloat16_as_ushort(__float2bfloat16(h1));
            sh[h * 8 + g] = (hi << 16) | lo;
        }
    }
    __syncthreads();

    // -------- Phase 2: second layer. Thread owns (nh, row-pair g). --------
    const int nh = t & 15;
    const int g  = t >> 4;
    float a0 = 0.f, a1 = 0.f;
    #pragma unroll 8
    for (int h = 0; h < HIDDEN; h++) {
        const float w = sW2[h * NHEAD + nh];               // broadcast across row-pairs
        const unsigned int p = sh[h * 8 + g];              // broadcast across nh
        const float hv0 = __ushort_as_bfloat16((unsigned short)(p & 0xFFFF));
        const float hv1 = __ushort_as_bfloat16((unsigned short)(p >> 16));
        a0 = fmaf(hv0, w, a0);
        a1 = fmaf(hv1, w, a1);
    }
    // fused activation: 16 * sigmoid(x)
    a0 = 16.f / (1.f + __expf(-a0));
    a1 = 16.f / (1.f + __expf(-a1));

    const int r0 = row0 + 2 * g;
    const int r1 = r0 + 1;
    if (r0 < NROW) g_rpt[nh * NROW + r0] = a0;
    if (r1 < NROW) g_rpt[nh * NROW + r1] = a1;
}

// ---------------------------------------------------------------------------
// Kernel 2: gather into [B, NH, TF*64, TP*64] with closed-form rpi index:
//   idx = (t_f + t_p)*225 + (h_f - h_p + 7)*15 + (w_f - w_p + 7)
// One thread per float4 of output (4 consecutive w_p -> idx, idx-1, idx-2, idx-3).
// All dims are powers of two: pure shift/mask indexing, 2^23 threads total.
// ---------------------------------------------------------------------------
__global__ void __launch_bounds__(256) gather_kernel(
    const int* __restrict__ ptc,     // [B, 8]  (non-positive; time = -ptc)
    const int* __restrict__ ftc,     // [B, 8]
    float4* __restrict__ out)        // [B, 16, 512, 512] / 4
{
    const int t   = blockIdx.x * 256 + threadIdx.x;  // 0 .. 2^23-1
    const int pk4 = t & 127;          // float4 index along pk (512/4)
    const int fq  = (t >> 7) & 511;   // tf*64 + hf*8 + wf
    const int nh  = (t >> 16) & 15;
    const int b   = t >> 20;

    const int pk  = pk4 << 2;
    const int wp0 = pk & 7;           // 0 or 4
    const int hp  = (pk >> 3) & 7;
    const int tp  = pk >> 6;

    const int wf = fq & 7;
    const int hf = (fq >> 3) & 7;
    const int tf = fq >> 6;

    const int t_f =  __ldg(ftc + b * 8 + tf);
    const int t_p = -__ldg(ptc + b * 8 + tp);

    // max base = 98*225 + 14*15 + 14 = 22274 = NROW-1; base-3 >= 4 always (w term >= 3+... )
    const int base = (t_f + t_p) * 225 + (hf - hp + 7) * 15 + (wf - wp0 + 7);

    const float* __restrict__ row = g_rpt + nh * NROW;
    float4 v;
    v.x = __ldg(row + base);
    v.y = __ldg(row + base - 1);
    v.z = __ldg(row + base - 2);
    v.w = __ldg(row + base - 3);
    out[t] = v;
}

// ---------------------------------------------------------------------------
// Launch. Input order (metadata): ptc, ftc, W1, b1, W2, rct, rpi_table.
// rpi_table is NOT read — the index is computed analytically.
// ---------------------------------------------------------------------------
extern "C" void kernel_launch(void* const* d_in, const int* in_sizes, int n_in,
                              void* d_out, int out_size)
{
    const int*   ptc = (const int*)  d_in[0];
    const int*   ftc = (const int*)  d_in[1];
    const float* W1  = (const float*)d_in[2];
    const float* b1  = (const float*)d_in[3];
    const float* W2  = (const float*)d_in[4];
    const float* rct = (const float*)d_in[5];

    // MLP: 22275 rows / 16 per block
    mlp_kernel<<<(NROW + 15) / 16, 128>>>(rct, W1, b1, W2);

    // Gather: out_size = 8*16*512*512 = 2^25 floats -> 2^23 float4 threads
    const int n4 = out_size / 4;
    gather_kernel<<<n4 / 256, 256>>>(ptc, ftc, (float4*)d_out);
}

// round 2
// speedup vs baseline: 1.5947x; 1.5947x over previous
#include <cuda_runtime.h>
#include <cuda_bf16.h>

// T=50, H=W=8, NH=16, B=8, TP=TF=8, HIDDEN=512, RPE_COEF=16
#define NROW   22275          // 99*15*15
#define NROWP  22288          // padded to mult of 16 for aligned STG.128
#define NHEAD  16
#define HIDDEN 512
#define HPAD   20             // smem row stride (floats): 80B -> conflict-free 128b ops

// Scratch: g_rpt[nh][row] = 16*sigmoid( (relu(rct@W1+b1)@W2)[row][nh] )
__device__ float g_rpt[NHEAD * NROWP];

// ---- packed f32x2 helpers (Blackwell) --------------------------------------
__device__ __forceinline__ unsigned long long pk64(float lo, float hi) {
    unsigned long long r;
    asm("mov.b64 %0, {%1, %2};" : "=l"(r) : "f"(lo), "f"(hi));
    return r;
}
__device__ __forceinline__ void upk64(unsigned long long v, float& lo, float& hi) {
    asm("mov.b64 {%0, %1}, %2;" : "=f"(lo), "=f"(hi) : "l"(v));
}
__device__ __forceinline__ unsigned long long fma2(unsigned long long a,
                                                   unsigned long long b,
                                                   unsigned long long c) {
    unsigned long long d;
    asm("fma.rn.f32x2 %0, %1, %2, %3;" : "=l"(d) : "l"(a), "l"(b), "l"(c));
    return d;
}

// ---------------------------------------------------------------------------
// Kernel 1: cpb MLP, fused 16*sigmoid, transposed store.
// 16 rows/block, 128 threads. Hidden kept fp32 in padded smem.
// Phase 2: each warp owns a 128-wide h slice; thread owns (nh, 8 rows);
// 4 x fma.rn.f32x2 per h; 4-way smem reduction at the end.
// ---------------------------------------------------------------------------
__global__ void __launch_bounds__(128) mlp_kernel(
    const float* __restrict__ rct,   // [NROW, 3]
    const float* __restrict__ W1,    // [3, 512]
    const float* __restrict__ b1,    // [512]
    const float* __restrict__ W2)    // [512, 16]
{
    __shared__ float sH[HIDDEN * HPAD];     // 40 KB: sH[h*HPAD + r], r in [0,16)
    const int t    = threadIdx.x;
    const int row0 = blockIdx.x * 16;

    // ---- Phase 1: hidden layer (fp32) ----
    {
        const int lane = t & 31;
        const int quad = t >> 5;            // rows quad*4 .. quad*4+3
        float c0[4], c1[4], c2[4];
        #pragma unroll
        for (int j = 0; j < 4; j++) {
            const int r = row0 + quad * 4 + j;
            if (r < NROW) {
                c0[j] = __ldg(rct + r * 3 + 0);
                c1[j] = __ldg(rct + r * 3 + 1);
                c2[j] = __ldg(rct + r * 3 + 2);
            } else { c0[j] = c1[j] = c2[j] = 0.f; }
        }
        #pragma unroll 4
        for (int i = 0; i < 16; i++) {
            const int h  = i * 32 + lane;
            const float w0 = __ldg(W1 + h);
            const float w1 = __ldg(W1 + HIDDEN + h);
            const float w2 = __ldg(W1 + 2 * HIDDEN + h);
            const float bb = __ldg(b1 + h);
            float4 hv;
            hv.x = fmaxf(fmaf(c2[0], w2, fmaf(c1[0], w1, fmaf(c0[0], w0, bb))), 0.f);
            hv.y = fmaxf(fmaf(c2[1], w2, fmaf(c1[1], w1, fmaf(c0[1], w0, bb))), 0.f);
            hv.z = fmaxf(fmaf(c2[2], w2, fmaf(c1[2], w1, fmaf(c0[2], w0, bb))), 0.f);
            hv.w = fmaxf(fmaf(c2[3], w2, fmaf(c1[3], w1, fmaf(c0[3], w0, bb))), 0.f);
            *reinterpret_cast<float4*>(&sH[h * HPAD + quad * 4]) = hv;
        }
    }
    __syncthreads();

    // ---- Phase 2: layer 2 with f32x2 FMA ----
    const int qtr  = t >> 5;                // warp id -> h slice [qtr*128, +128)
    const int lane = t & 31;
    const int oct  = lane >> 4;             // rows oct*8 .. oct*8+7
    const int nh   = lane & 15;
    unsigned long long acc0 = 0ull, acc1 = 0ull, acc2 = 0ull, acc3 = 0ull;
    const int h0 = qtr * 128;
    const float* __restrict__ w2p = W2 + nh;
    #pragma unroll 4
    for (int i = 0; i < 128; i++) {
        const int h = h0 + i;
        const float w = __ldg(w2p + h * NHEAD);          // L1-resident (32 KB)
        const unsigned long long ww = pk64(w, w);
        const float4 ha = *reinterpret_cast<const float4*>(&sH[h * HPAD + oct * 8]);
        const float4 hb = *reinterpret_cast<const float4*>(&sH[h * HPAD + oct * 8 + 4]);
        acc0 = fma2(pk64(ha.x, ha.y), ww, acc0);
        acc1 = fma2(pk64(ha.z, ha.w), ww, acc1);
        acc2 = fma2(pk64(hb.x, hb.y), ww, acc2);
        acc3 = fma2(pk64(hb.z, hb.w), ww, acc3);
    }
    __syncthreads();                         // done reading sH: reuse for reduction

    float a[8];
    upk64(acc0, a[0], a[1]); upk64(acc1, a[2], a[3]);
    upk64(acc2, a[4], a[5]); upk64(acc3, a[6], a[7]);

    float* sRed = sH;                        // [qtr][lane][8]
    if (qtr > 0) {
        #pragma unroll
        for (int j = 0; j < 8; j++) sRed[(qtr * 32 + lane) * 8 + j] = a[j];
    }
    __syncthreads();
    if (qtr == 0) {
        #pragma unroll
        for (int q = 1; q < 4; q++)
            #pragma unroll
            for (int j = 0; j < 8; j++) a[j] += sRed[(q * 32 + lane) * 8 + j];
        #pragma unroll
        for (int j = 0; j < 8; j++) a[j] = 16.f / (1.f + __expf(-a[j]));
        float* dst = g_rpt + nh * NROWP + row0 + oct * 8;
        *reinterpret_cast<float4*>(dst)     = make_float4(a[0], a[1], a[2], a[3]);
        *reinterpret_cast<float4*>(dst + 4) = make_float4(a[4], a[5], a[6], a[7]);
    }
}

// ---------------------------------------------------------------------------
// Kernel 2: gather. One block per (b, nh, tf, tp) tile = 64x64 output floats.
// The tile reads only 225 table floats: stage them in smem, then pure
// coalesced streaming STG.128 writes. Closed-form rpi index:
//   idx = (t_f + t_p)*225 + (hf-hp+7)*15 + (wf-wp+7)
// ---------------------------------------------------------------------------
__global__ void __launch_bounds__(256) gather_kernel(
    const int* __restrict__ ptc,     // [B, 8] (non-positive; time = -ptc)
    const int* __restrict__ ftc,     // [B, 8]
    float4* __restrict__ out)        // [B, 16, 512, 512] / 4
{
    __shared__ float s[225];
    const int blk = blockIdx.x;
    const int tp = blk & 7;
    const int tf = (blk >> 3) & 7;
    const int nh = (blk >> 6) & 15;
    const int b  = blk >> 10;

    const int t_f =  __ldg(ftc + b * 8 + tf);
    const int t_p = -__ldg(ptc + b * 8 + tp);
    const float* __restrict__ src = g_rpt + nh * NROWP + (t_f + t_p) * 225;
    if (threadIdx.x < 225) s[threadIdx.x] = __ldg(src + threadIdx.x);
    __syncthreads();

    // output tile base (as float4 index): ((b*16+nh)*512 + tf*64)*512 + tp*64
    float4* __restrict__ out4 =
        out + ((((b * NHEAD + nh) * 512 + tf * 64) * 512 + tp * 64) >> 2);

    #pragma unroll
    for (int k = 0; k < 4; k++) {
        const int j   = threadIdx.x + k * 256;   // 0..1023 = 64 rows x 16 float4
        const int c4  = j & 15;                  // float4 within row
        const int fhw = j >> 4;                  // output row 0..63
        const int wf  = fhw & 7;
        const int hf  = (fhw >> 3) & 7;
        const int phw = c4 << 2;
        const int wp0 = phw & 7;                 // 0 or 4
        const int hp  = phw >> 3;
        const int si  = (hf - hp + 7) * 15 + (wf - wp0 + 7);
        float4 v;
        v.x = s[si];     v.y = s[si - 1];
        v.z = s[si - 2]; v.w = s[si - 3];
        __stcs(out4 + fhw * 128 + c4, v);        // streaming: don't pollute L2
    }
}

// ---------------------------------------------------------------------------
// Launch. Input order: ptc, ftc, W1, b1, W2, rct, rpi_table (unused).
// ---------------------------------------------------------------------------
extern "C" void kernel_launch(void* const* d_in, const int* in_sizes, int n_in,
                              void* d_out, int out_size)
{
    const int*   ptc = (const int*)  d_in[0];
    const int*   ftc = (const int*)  d_in[1];
    const float* W1  = (const float*)d_in[2];
    const float* b1  = (const float*)d_in[3];
    const float* W2  = (const float*)d_in[4];
    const float* rct = (const float*)d_in[5];

    mlp_kernel<<<NROWP / 16, 128>>>(rct, W1, b1, W2);

    // 8192 blocks: one per (b, nh, tf, tp) 64x64 tile
    gather_kernel<<<8 * NHEAD * 8 * 8, 256>>>(ptc, ftc, (float4*)d_out);
}